// round 12
// baseline (speedup 1.0000x reference)
#include <cuda_runtime.h>
#include <cstdint>

#define RNODES 256
#define LUTWORDS 8192        // 2^18 bits / 32
#define MSAMP 512
#define SSTEPS 512
#define NIN 32               // D*B
#define NOUT 10
#define SPC 4                // samples per CTA
#define NCTA (MSAMP / SPC)   // 128 -> single wave, 1 CTA per SM

// Persistent scratch (device globals — no runtime allocation allowed)
__device__ unsigned g_lutpk[RNODES * LUTWORDS];   // 8 MB bit-packed LUT
__device__ unsigned g_xbits[MSAMP * SSTEPS];      // 1 MB: 32 input bits per (m,t)
__device__ unsigned g_Wlo8[RNODES * 64];          // row-major lo bytes of primes*W (u32 = 4 k)
__device__ unsigned g_Whi8[RNODES * 64];          // row-major hi bytes (values 0..6)

// ---------------------------------------------------------------------------
// Per-warp bool-serialization detect: if x is int32-encoded, every byte at
// offset%4!=0 is zero. u8-encoded random bits false-negative prob ~2^-96.
// ---------------------------------------------------------------------------
__device__ __forceinline__ int detect_u8(const void* xraw) {
    const unsigned char* p = (const unsigned char*)xraw;
    unsigned lane = threadIdx.x & 31u;
    unsigned acc = 0;
    for (unsigned i = lane; i < 128; i += 32)
        if (i & 3) acc |= p[i];
    return __ballot_sync(0xffffffffu, acc != 0) != 0;
}

// ---------------------------------------------------------------------------
// Pack the 256MB int32 0/1 LUT into 8MB of bits. 8 elements/thread, 32768
// CTAs (262144 CTAs was CTA-launch-rate bound). DRAM-floor bound (~44us).
// ---------------------------------------------------------------------------
__global__ void k_lutpack(const int* __restrict__ lut) {
    unsigned T = blockIdx.x * 256u + threadIdx.x;          // 8,388,608 threads
    unsigned v[8];
#pragma unroll
    for (int i = 0; i < 8; i++)
        v[i] = (unsigned)lut[T + (unsigned)i * 8388608u];
    unsigned wbase = T >> 5;
#pragma unroll
    for (int i = 0; i < 8; i++) {
        unsigned m = __ballot_sync(0xffffffffu, v[i] & 1u);
        if ((threadIdx.x & 31u) == 0u)
            g_lutpk[wbase + (unsigned)i * 262144u] = m;
    }
}

// ---------------------------------------------------------------------------
// Fused prep: x bit-packing (grid-stride) + weight prep into row-major
// byte matrices for IMMA A-fragments:
//   Wlo8[j][c] = 4 lo bytes of primes*W for k=4c..4c+3
//   Whi8[j][c] = 4 hi bytes (prime>>8, 0..6)
// ---------------------------------------------------------------------------
__global__ void k_prep(const void* __restrict__ xraw,
                       const void* __restrict__ wraw,
                       const int* __restrict__ primes) {
    const int flag = detect_u8(xraw);

    // ---- xpack: 8,388,608 bools -> 262,144 u32 words
    for (unsigned g = blockIdx.x * 256u + threadIdx.x;
         g < MSAMP * SSTEPS * 32u; g += 1024u * 256u) {
        unsigned v;
        if (flag) v = ((const unsigned char*)xraw)[g] & 1u;
        else      v = (unsigned)((const int*)xraw)[g] & 1u;
        unsigned m = __ballot_sync(0xffffffffu, v);
        if ((threadIdx.x & 31u) == 0u) g_xbits[g >> 5] = m;
    }

    // ---- wprep
    int t = blockIdx.x * 256 + threadIdx.x;
    if (t < RNODES * 8) {
        int j = t >> 3, w8 = t & 7;
        unsigned lo[8] = {0, 0, 0, 0, 0, 0, 0, 0};
        unsigned hi[8] = {0, 0, 0, 0, 0, 0, 0, 0};
        for (int kk = 0; kk < 32; kk++) {
            int k = w8 * 32 + kk;
            unsigned wv = flag ? (unsigned)(((const unsigned char*)wraw)[j * RNODES + k] & 1)
                               : ((unsigned)((const int*)wraw)[j * RNODES + k] & 1u);
            unsigned p = wv ? (unsigned)primes[k] : 0u;
            lo[kk >> 2] |= (p & 255u) << ((kk & 3) * 8);
            hi[kk >> 2] |= (p >> 8) << ((kk & 3) * 8);
        }
        for (int cc = 0; cc < 8; cc++) {
            g_Wlo8[j * 64 + w8 * 8 + cc] = lo[cc];
            g_Whi8[j * 64 + w8 * 8 + cc] = hi[cc];
        }
    }
}

// ---------------------------------------------------------------------------
// Main reservoir kernel, tensor-core edition.
// 128 CTAs x 256 threads, 4 samples per CTA. Per step the 256x256 u8 matvec
// for all 4 samples is one m16n8k32 IMMA sweep: warp w owns nodes
// [32w, 32w+32) as two 16-row M-tiles; A lo/hi fragments live in registers
// across all 512 steps; B (0/1 state bytes, 8 cols: samples 0..3 real) is
// rebuilt each step from 8 ballot words via nibble->byte expansion.
// idx = Clo + (Chi<<8) exactly (prime = lo + 256*hi). LUT probes by the
// q<2 lanes (those holding real sample columns), 8 probes each.
// ---------------------------------------------------------------------------
__global__ void __launch_bounds__(256, 1)
k_main(const void* __restrict__ xraw,
       const int* __restrict__ input_nodes,
       const void* __restrict__ initraw,
       const float* __restrict__ rW,
       const float* __restrict__ rb,
       float* __restrict__ out)
{
    __shared__ unsigned s_x[SPC][SSTEPS];                  // 8 KB
    __shared__ unsigned char s_rbytes[SPC][RNODES];        // 1 KB state bytes
    __shared__ __align__(16) unsigned s_rbits[SPC][8];     // state bit-words

    const int m0 = blockIdx.x * SPC;
    const int tid = threadIdx.x;
    const int lane = tid & 31, w = tid >> 5;
    const int g = lane >> 2, q = lane & 3;   // groupID / threadID-in-group

    // stage all samples' packed inputs
#pragma unroll
    for (int s = 0; s < SPC; s++)
        for (int i = tid; i < SSTEPS; i += 256)
            s_x[s][i] = g_xbits[(m0 + s) * SSTEPS + i];

    // A fragments (static across all steps). m16n8k32 row-major u8 layout:
    // a0:(row=g,    k=q*4..+3)  a1:(row=g+8, same k)
    // a2:(row=g,    k=16+q*4)   a3:(row=g+8, k=16+q*4)
    unsigned Alo[2][8][4], Ahi[2][8][4];
#pragma unroll
    for (int mt = 0; mt < 2; mt++)
#pragma unroll
        for (int kt = 0; kt < 8; kt++) {
            int nb = w * 32 + mt * 16 + g;
            int wi = kt * 8 + q;
            Alo[mt][kt][0] = g_Wlo8[nb * 64 + wi];
            Alo[mt][kt][1] = g_Wlo8[(nb + 8) * 64 + wi];
            Alo[mt][kt][2] = g_Wlo8[nb * 64 + wi + 4];
            Alo[mt][kt][3] = g_Wlo8[(nb + 8) * 64 + wi + 4];
            Ahi[mt][kt][0] = g_Whi8[nb * 64 + wi];
            Ahi[mt][kt][1] = g_Whi8[(nb + 8) * 64 + wi];
            Ahi[mt][kt][2] = g_Whi8[nb * 64 + wi + 4];
            Ahi[mt][kt][3] = g_Whi8[(nb + 8) * 64 + wi + 4];
        }

    // probe-node metadata (used by q<2 lanes): C rows g/g+8 of each M-tile
    int nd[4];
    nd[0] = w * 32 + g;       nd[1] = nd[0] + 8;
    nd[2] = w * 32 + 16 + g;  nd[3] = nd[2] + 8;
    int isin[4] = {0, 0, 0, 0}, ipos[4] = {0, 0, 0, 0};
    for (int i = 0; i < NIN; i++) {
        int n = input_nodes[i];
#pragma unroll
        for (int k = 0; k < 4; k++)
            if (n == nd[k]) { isin[k] = 1; ipos[k] = i; }
    }

    const int flag = detect_u8(xraw);

    // ---- prologue: state 0 (init overridden by x[0] on input nodes)
    {
        int isin_t = 0, ipos_t = 0;
        for (int i = 0; i < NIN; i++)
            if (input_nodes[i] == tid) { isin_t = 1; ipos_t = i; }
        unsigned rin = flag ? (unsigned)(((const unsigned char*)initraw)[tid] & 1)
                            : ((unsigned)((const int*)initraw)[tid] & 1u);
        __syncthreads();   // s_x visible
#pragma unroll
        for (int s = 0; s < SPC; s++) {
            unsigned b = isin_t ? ((s_x[s][0] >> ipos_t) & 1u) : rin;
            s_rbytes[s][tid] = (unsigned char)b;
        }
    }
    __syncthreads();
    if (w < 4) {
#pragma unroll
        for (int kt = 0; kt < 8; kt++) {
            unsigned bt = s_rbytes[w][kt * 32 + lane];
            unsigned bb = __ballot_sync(0xffffffffu, bt & 1u);
            if (lane == 0) s_rbits[w][kt] = bb;
        }
    }
    __syncthreads();

    const int sAq = q * 2, sBq = sAq + 1;    // real sample columns for q<2

    for (int t = 0; t < SSTEPS; t++) {
        // own-sample state bits (B col = g; cols 4..7 are zero padding)
        unsigned rw[8];
        if (g < 4) {
            uint4 hA = *(const uint4*)&s_rbits[g][0];
            uint4 hB = *(const uint4*)&s_rbits[g][4];
            rw[0] = hA.x; rw[1] = hA.y; rw[2] = hA.z; rw[3] = hA.w;
            rw[4] = hB.x; rw[5] = hB.y; rw[6] = hB.z; rw[7] = hB.w;
        } else {
#pragma unroll
            for (int i2 = 0; i2 < 8; i2++) rw[i2] = 0;
        }

        // B fragments: b0 k=q*4..+3, b1 k=16+q*4..+3; byte i = bit i
        unsigned Bf[8][2];
#pragma unroll
        for (int kt = 0; kt < 8; kt++) {
            unsigned v0 = (rw[kt] >> (q * 4)) & 0xFu;
            unsigned v1 = (rw[kt] >> (16 + q * 4)) & 0xFu;
            Bf[kt][0] = (v0 * 0x00204081u) & 0x01010101u;
            Bf[kt][1] = (v1 * 0x00204081u) & 0x01010101u;
        }

        // IMMA sweep: 2 M-tiles x 8 K-tiles x {lo,hi}
        unsigned Clo[2][4], Chi[2][4];
#pragma unroll
        for (int mt = 0; mt < 2; mt++)
#pragma unroll
            for (int r4 = 0; r4 < 4; r4++) { Clo[mt][r4] = 0u; Chi[mt][r4] = 0u; }
#pragma unroll
        for (int mt = 0; mt < 2; mt++)
#pragma unroll
            for (int kt = 0; kt < 8; kt++) {
                asm volatile(
                    "mma.sync.aligned.m16n8k32.row.col.s32.u8.u8.s32 "
                    "{%0,%1,%2,%3}, {%4,%5,%6,%7}, {%8,%9}, {%0,%1,%2,%3};"
                    : "+r"(Clo[mt][0]), "+r"(Clo[mt][1]), "+r"(Clo[mt][2]), "+r"(Clo[mt][3])
                    : "r"(Alo[mt][kt][0]), "r"(Alo[mt][kt][1]),
                      "r"(Alo[mt][kt][2]), "r"(Alo[mt][kt][3]),
                      "r"(Bf[kt][0]), "r"(Bf[kt][1]));
                asm volatile(
                    "mma.sync.aligned.m16n8k32.row.col.s32.u8.u8.s32 "
                    "{%0,%1,%2,%3}, {%4,%5,%6,%7}, {%8,%9}, {%0,%1,%2,%3};"
                    : "+r"(Chi[mt][0]), "+r"(Chi[mt][1]), "+r"(Chi[mt][2]), "+r"(Chi[mt][3])
                    : "r"(Ahi[mt][kt][0]), "r"(Ahi[mt][kt][1]),
                      "r"(Ahi[mt][kt][2]), "r"(Ahi[mt][kt][3]),
                      "r"(Bf[kt][0]), "r"(Bf[kt][1]));
            }

        // probes: q<2 lanes hold the real sample columns (C cols q*2, q*2+1)
        if (q < 2) {
            unsigned xwA = 0, xwB = 0;
            if (t + 1 < SSTEPS) { xwA = s_x[sAq][t + 1]; xwB = s_x[sBq][t + 1]; }
#pragma unroll
            for (int mt = 0; mt < 2; mt++) {
                unsigned i00 = Clo[mt][0] + (Chi[mt][0] << 8);   // (nd[2mt],   sA)
                unsigned i01 = Clo[mt][1] + (Chi[mt][1] << 8);   // (nd[2mt],   sB)
                unsigned i10 = Clo[mt][2] + (Chi[mt][2] << 8);   // (nd[2mt+1], sA)
                unsigned i11 = Clo[mt][3] + (Chi[mt][3] << 8);   // (nd[2mt+1], sB)
                const unsigned* lp0 = g_lutpk + ((unsigned)nd[mt * 2] << 13);
                const unsigned* lp1 = g_lutpk + ((unsigned)nd[mt * 2 + 1] << 13);
                unsigned w00 = __ldg(lp0 + (i00 >> 5));
                unsigned w01 = __ldg(lp0 + (i01 >> 5));
                unsigned w10 = __ldg(lp1 + (i10 >> 5));
                unsigned w11 = __ldg(lp1 + (i11 >> 5));
                unsigned b00 = (w00 >> (i00 & 31u)) & 1u;
                unsigned b01 = (w01 >> (i01 & 31u)) & 1u;
                unsigned b10 = (w10 >> (i10 & 31u)) & 1u;
                unsigned b11 = (w11 >> (i11 & 31u)) & 1u;
                if (t + 1 < SSTEPS) {
                    if (isin[mt * 2]) {
                        b00 = (xwA >> ipos[mt * 2]) & 1u;
                        b01 = (xwB >> ipos[mt * 2]) & 1u;
                    }
                    if (isin[mt * 2 + 1]) {
                        b10 = (xwA >> ipos[mt * 2 + 1]) & 1u;
                        b11 = (xwB >> ipos[mt * 2 + 1]) & 1u;
                    }
                }
                s_rbytes[sAq][nd[mt * 2]]     = (unsigned char)b00;
                s_rbytes[sBq][nd[mt * 2]]     = (unsigned char)b01;
                s_rbytes[sAq][nd[mt * 2 + 1]] = (unsigned char)b10;
                s_rbytes[sBq][nd[mt * 2 + 1]] = (unsigned char)b11;
            }
        }
        __syncthreads();

        // rebuild bit-words (warp w < 4 handles sample w)
        if (w < 4) {
#pragma unroll
            for (int kt = 0; kt < 8; kt++) {
                unsigned bt = s_rbytes[w][kt * 32 + lane];
                unsigned bb = __ballot_sync(0xffffffffu, bt & 1u);
                if (lane == 0) s_rbits[w][kt] = bb;
            }
        }
        __syncthreads();
    }

    // readout: out[m, o] = sum_j rW[o, j] * rf[j] + rb[o]
    if (tid < SPC * 16) {                      // 64 threads: sample = tid/16, out = tid%16
        int s = tid >> 4, o = tid & 15;
        if (o < NOUT) {
            const unsigned char* rf = s_rbytes[s];
            float acc = rb[o];
            const float* wr = rW + o * RNODES;
            for (int k = 0; k < RNODES; k++)
                acc += wr[k] * (float)rf[k];
            out[(m0 + s) * NOUT + o] = acc;
        }
    }
}

// ---------------------------------------------------------------------------
// d_in order: x, input_nodes, lut, W_res, primes, init_res, readout_W, readout_b
// ---------------------------------------------------------------------------
extern "C" void kernel_launch(void* const* d_in, const int* in_sizes, int n_in,
                              void* d_out, int out_size) {
    (void)in_sizes; (void)n_in; (void)out_size;
    const void*  x       = d_in[0];
    const int*   innodes = (const int*)d_in[1];
    const int*   lut     = (const int*)d_in[2];
    const void*  wres    = d_in[3];
    const int*   primes  = (const int*)d_in[4];
    const void*  initres = d_in[5];
    const float* rW      = (const float*)d_in[6];
    const float* rb      = (const float*)d_in[7];
    float* out = (float*)d_out;

    k_lutpack<<<32768, 256>>>(lut);
    k_prep<<<1024, 256>>>(x, wres, primes);
    k_main<<<NCTA, 256>>>(x, innodes, initres, rW, rb, out);
}

// round 13
// speedup vs baseline: 1.3315x; 1.3315x over previous
#include <cuda_runtime.h>
#include <cstdint>

#define RNODES 256
#define LUTWORDS 8192        // 2^18 bits / 32
#define MSAMP 512
#define SSTEPS 512
#define NIN 32               // D*B
#define NOUT 10
#define SPC 2                // samples per CTA
#define NCTA (MSAMP / SPC)   // 256 CTAs, occ 2 -> single wave

// Persistent scratch (device globals — no runtime allocation allowed)
__device__ unsigned g_lutpk[RNODES * LUTWORDS];   // 8 MB bit-packed LUT
__device__ unsigned g_xbits[MSAMP * SSTEPS];      // 1 MB: 32 input bits per (m,t)
__device__ unsigned g_Wlo[64 * RNODES];           // chunk-major low bytes of primes*W
__device__ unsigned g_hib[24 * RNODES];           // [b(0..2)][w(0..7)][j] hi bitplanes

// ---------------------------------------------------------------------------
// Per-warp bool-serialization detect: if x is int32-encoded, every byte at
// offset%4!=0 is zero. u8-encoded random bits false-negative prob ~2^-96.
// ---------------------------------------------------------------------------
__device__ __forceinline__ int detect_u8(const void* xraw) {
    const unsigned char* p = (const unsigned char*)xraw;
    unsigned lane = threadIdx.x & 31u;
    unsigned acc = 0;
    for (unsigned i = lane; i < 128; i += 32)
        if (i & 3) acc |= p[i];
    return __ballot_sync(0xffffffffu, acc != 0) != 0;
}

// ---------------------------------------------------------------------------
// Pack the 256MB int32 0/1 LUT into 8MB of bits. 8 elements/thread, 32768
// CTAs (262144 CTAs was CTA-launch-rate bound). DRAM-floor bound (~44us).
// ---------------------------------------------------------------------------
__global__ void k_lutpack(const int* __restrict__ lut) {
    unsigned T = blockIdx.x * 256u + threadIdx.x;          // 8,388,608 threads
    unsigned v[8];
#pragma unroll
    for (int i = 0; i < 8; i++)
        v[i] = (unsigned)lut[T + (unsigned)i * 8388608u];
    unsigned wbase = T >> 5;
#pragma unroll
    for (int i = 0; i < 8; i++) {
        unsigned m = __ballot_sync(0xffffffffu, v[i] & 1u);
        if ((threadIdx.x & 31u) == 0u)
            g_lutpk[wbase + (unsigned)i * 262144u] = m;
    }
}

// ---------------------------------------------------------------------------
// Fused prep: x bit-packing (grid-stride) + weight prep.
//   lo = Wp & 255  -> chunk-major u32 (4 bytes of k per word) for dp4a
//   hi = Wp >> 8 (0..6) -> 3 bitplanes over k, 8 words of 32 bits each
// ---------------------------------------------------------------------------
__global__ void k_prep(const void* __restrict__ xraw,
                       const void* __restrict__ wraw,
                       const int* __restrict__ primes) {
    const int flag = detect_u8(xraw);

    // ---- xpack: 8,388,608 bools -> 262,144 u32 words
    for (unsigned g = blockIdx.x * 256u + threadIdx.x;
         g < MSAMP * SSTEPS * 32u; g += 1024u * 256u) {
        unsigned v;
        if (flag) v = ((const unsigned char*)xraw)[g] & 1u;
        else      v = (unsigned)((const int*)xraw)[g] & 1u;
        unsigned m = __ballot_sync(0xffffffffu, v);
        if ((threadIdx.x & 31u) == 0u) g_xbits[g >> 5] = m;
    }

    // ---- wprep
    int t = blockIdx.x * 256 + threadIdx.x;
    if (t < RNODES * 8) {
        int j = t >> 3, w = t & 7;
        unsigned lo[8] = {0, 0, 0, 0, 0, 0, 0, 0};
        unsigned hb0 = 0, hb1 = 0, hb2 = 0;
        for (int kk = 0; kk < 32; kk++) {
            int k = w * 32 + kk;
            unsigned wv = flag ? (unsigned)(((const unsigned char*)wraw)[j * RNODES + k] & 1)
                               : ((unsigned)((const int*)wraw)[j * RNODES + k] & 1u);
            unsigned p = wv ? (unsigned)primes[k] : 0u;
            lo[kk >> 2] |= (p & 255u) << ((kk & 3) * 8);
            unsigned h = p >> 8;
            hb0 |= (h & 1u) << kk;
            hb1 |= ((h >> 1) & 1u) << kk;
            hb2 |= ((h >> 2) & 1u) << kk;
        }
        for (int cc = 0; cc < 8; cc++)
            g_Wlo[(w * 8 + cc) * RNODES + j] = lo[cc];
        g_hib[(0 * 8 + w) * RNODES + j] = hb0;
        g_hib[(1 * 8 + w) * RNODES + j] = hb1;
        g_hib[(2 * 8 + w) * RNODES + j] = hb2;
    }
}

// ---------------------------------------------------------------------------
// Main reservoir kernel: 2 samples per CTA, 256 CTAs, 256 threads, occ 2
// (single wave; ~112 live regs fits the 128-reg cap without spills).
// Two resident CTAs per SM overlap each other's barrier/gather stalls.
// Within a CTA the two samples are software-pipelined: while sample B
// computes its index, sample A's LUT gather drains, and vice versa.
// ---------------------------------------------------------------------------
__global__ void __launch_bounds__(256, 2)
k_main(const void* __restrict__ xraw,
       const int* __restrict__ input_nodes,
       const void* __restrict__ initraw,
       const float* __restrict__ rW,
       const float* __restrict__ rb,
       float* __restrict__ out)
{
    __shared__ unsigned s_x[SPC][SSTEPS];                      // 4 KB
    __shared__ __align__(16) uint4 s_r4[SPC][16];              // 256B r-bytes per sample
    __shared__ __align__(16) unsigned s_rbits[SPC][8];         // r-bits per sample

    const int m0 = blockIdx.x * SPC;
    const int j = threadIdx.x;
    const int lane = j & 31, warp = j >> 5;

    // stage both samples' packed inputs
#pragma unroll
    for (int s = 0; s < SPC; s++)
        for (int i = j; i < SSTEPS; i += 256)
            s_x[s][i] = g_xbits[(m0 + s) * SSTEPS + i];

    // weights into registers (static across all 512 steps)
    unsigned Wlo[64];
#pragma unroll
    for (int c = 0; c < 64; c++) Wlo[c] = g_Wlo[c * RNODES + j];
    unsigned HB0[8], HB1[8], HB2[8];
#pragma unroll
    for (int w = 0; w < 8; w++) {
        HB0[w] = g_hib[(0 * 8 + w) * RNODES + j];
        HB1[w] = g_hib[(1 * 8 + w) * RNODES + j];
        HB2[w] = g_hib[(2 * 8 + w) * RNODES + j];
    }

    int isin = 0, ipos = 0;
    for (int i = 0; i < NIN; i++) {
        int n = input_nodes[i];
        if (n == j) { isin = 1; ipos = i; }
    }

    const int flag = detect_u8(xraw);
    unsigned rinit = flag ? (unsigned)(((const unsigned char*)initraw)[j] & 1)
                          : ((unsigned)((const int*)initraw)[j] & 1u);
    unsigned r0 = rinit, r1 = rinit;

    const unsigned* lutp = g_lutpk + ((unsigned)j << 13);

    // dot for one sample from published shared state
    auto dot = [&](int s) -> unsigned {
        const uint4* q = s_r4[s];
        unsigned a0 = 0, a1 = 0, a2 = 0, a3 = 0;
#pragma unroll
        for (int c = 0; c < 16; c++) {
            uint4 v = q[c];
            a0 = __dp4a(v.x, Wlo[4 * c + 0], a0);
            a1 = __dp4a(v.y, Wlo[4 * c + 1], a1);
            a2 = __dp4a(v.z, Wlo[4 * c + 2], a2);
            a3 = __dp4a(v.w, Wlo[4 * c + 3], a3);
        }
        uint4 hA = *(const uint4*)&s_rbits[s][0];
        uint4 hB = *(const uint4*)&s_rbits[s][4];
        unsigned rw0 = hA.x, rw1 = hA.y, rw2 = hA.z, rw3 = hA.w;
        unsigned rw4 = hB.x, rw5 = hB.y, rw6 = hB.z, rw7 = hB.w;
        unsigned h0 = __popc(rw0 & HB0[0]) + __popc(rw1 & HB0[1]) +
                      __popc(rw2 & HB0[2]) + __popc(rw3 & HB0[3]) +
                      __popc(rw4 & HB0[4]) + __popc(rw5 & HB0[5]) +
                      __popc(rw6 & HB0[6]) + __popc(rw7 & HB0[7]);
        unsigned h1 = __popc(rw0 & HB1[0]) + __popc(rw1 & HB1[1]) +
                      __popc(rw2 & HB1[2]) + __popc(rw3 & HB1[3]) +
                      __popc(rw4 & HB1[4]) + __popc(rw5 & HB1[5]) +
                      __popc(rw6 & HB1[6]) + __popc(rw7 & HB1[7]);
        unsigned h2 = __popc(rw0 & HB2[0]) + __popc(rw1 & HB2[1]) +
                      __popc(rw2 & HB2[2]) + __popc(rw3 & HB2[3]) +
                      __popc(rw4 & HB2[4]) + __popc(rw5 & HB2[5]) +
                      __popc(rw6 & HB2[6]) + __popc(rw7 & HB2[7]);
        return (a0 + a1) + (a2 + a3) + ((h0 + 2u * h1 + 4u * h2) << 8);
    };
    auto publish = [&](int s, unsigned r) {
        unsigned b = __ballot_sync(0xffffffffu, r);
        ((unsigned char*)s_r4[s])[j] = (unsigned char)r;
        if (lane == 0) s_rbits[s][warp] = b;
    };

    __syncthreads();   // s_x visible

    // ---- prologue: apply input overwrite at t=0, publish both samples
    {
        if (isin) {
            r0 = (s_x[0][0] >> ipos) & 1u;
            r1 = (s_x[1][0] >> ipos) & 1u;
        }
        publish(0, r0); publish(1, r1);
    }
    __syncthreads();

    // prime sample 0: idx + gather for step 0
    unsigned idx0 = dot(0);
    unsigned wv0 = __ldg(lutp + (idx0 >> 5));
    __syncthreads();   // pre-loop reads of s_r4[0] done before loop rewrites it

    for (int t = 0; t < SSTEPS; t++) {
        // ---- phase 1: sample 1 compute+gather for step t (s0 load drains)
        unsigned idx1 = dot(1);
        unsigned wv1 = __ldg(lutp + (idx1 >> 5));

        // consume s0(step t) -> state t+1, overwrite, publish
        r0 = (wv0 >> (idx0 & 31u)) & 1u;
        if (isin && t + 1 < SSTEPS)
            r0 = (s_x[0][t + 1] >> ipos) & 1u;
        publish(0, r0);
        __syncthreads();

        // ---- phase 2: sample 0 compute+gather for step t+1 (s1 load drains)
        idx0 = dot(0);
        wv0 = __ldg(lutp + (idx0 >> 5));

        // consume s1(step t) -> state t+1, overwrite, publish
        r1 = (wv1 >> (idx1 & 31u)) & 1u;
        if (isin && t + 1 < SSTEPS)
            r1 = (s_x[1][t + 1] >> ipos) & 1u;
        publish(1, r1);
        __syncthreads();
    }

    // final states of both samples are published in s_r4
    // readout: out[m, o] = sum_j rW[o, j] * rf[j] + rb[o]
    if (j < SPC * 16) {                        // 32 threads: sample = j/16, out = j%16
        int s = j >> 4, o = j & 15;
        if (o < NOUT) {
            const unsigned char* rf = (const unsigned char*)s_r4[s];
            float acc = rb[o];
            const float* wr = rW + o * RNODES;
            for (int k = 0; k < RNODES; k++)
                acc += wr[k] * (float)rf[k];
            out[(m0 + s) * NOUT + o] = acc;
        }
    }
}

// ---------------------------------------------------------------------------
// d_in order: x, input_nodes, lut, W_res, primes, init_res, readout_W, readout_b
// ---------------------------------------------------------------------------
extern "C" void kernel_launch(void* const* d_in, const int* in_sizes, int n_in,
                              void* d_out, int out_size) {
    (void)in_sizes; (void)n_in; (void)out_size;
    const void*  x       = d_in[0];
    const int*   innodes = (const int*)d_in[1];
    const int*   lut     = (const int*)d_in[2];
    const void*  wres    = d_in[3];
    const int*   primes  = (const int*)d_in[4];
    const void*  initres = d_in[5];
    const float* rW      = (const float*)d_in[6];
    const float* rb      = (const float*)d_in[7];
    float* out = (float*)d_out;

    k_lutpack<<<32768, 256>>>(lut);
    k_prep<<<1024, 256>>>(x, wres, primes);
    k_main<<<NCTA, 256>>>(x, innodes, initres, rW, rb, out);
}

// round 15
// speedup vs baseline: 1.8125x; 1.3613x over previous
#include <cuda_runtime.h>
#include <cstdint>

#define RNODES 256
#define LUTWORDS 8192        // 2^18 bits / 32
#define MSAMP 512
#define SSTEPS 512
#define NIN 32               // D*B
#define NOUT 10
#define SPC 4                // samples per CTA
#define NCTA (MSAMP / SPC)   // 128 CTAs -> single wave

// Persistent scratch (device globals — no runtime allocation allowed)
__device__ unsigned g_lutpk[RNODES * LUTWORDS];   // 8 MB bit-packed LUT
__device__ unsigned g_xbits[MSAMP * SSTEPS];      // 1 MB: 32 input bits per (m,t)
__device__ unsigned g_Wlo[64 * RNODES];           // chunk-major low bytes of primes*W
__device__ unsigned g_hib[24 * RNODES];           // [b(0..2)][w(0..7)][j] hi bitplanes

// ---------------------------------------------------------------------------
// Per-warp bool-serialization detect: if x is int32-encoded, every byte at
// offset%4!=0 is zero. u8-encoded random bits false-negative prob ~2^-96.
// ---------------------------------------------------------------------------
__device__ __forceinline__ int detect_u8(const void* xraw) {
    const unsigned char* p = (const unsigned char*)xraw;
    unsigned lane = threadIdx.x & 31u;
    unsigned acc = 0;
    for (unsigned i = lane; i < 128; i += 32)
        if (i & 3) acc |= p[i];
    return __ballot_sync(0xffffffffu, acc != 0) != 0;
}

// ---------------------------------------------------------------------------
// Pack the 256MB int32 0/1 LUT into 8MB of bits. 8 elements/thread, 32768
// CTAs (262144 CTAs was CTA-launch-rate bound). DRAM-floor bound (~44us).
// ---------------------------------------------------------------------------
__global__ void k_lutpack(const int* __restrict__ lut) {
    unsigned T = blockIdx.x * 256u + threadIdx.x;          // 8,388,608 threads
    unsigned v[8];
#pragma unroll
    for (int i = 0; i < 8; i++)
        v[i] = (unsigned)lut[T + (unsigned)i * 8388608u];
    unsigned wbase = T >> 5;
#pragma unroll
    for (int i = 0; i < 8; i++) {
        unsigned m = __ballot_sync(0xffffffffu, v[i] & 1u);
        if ((threadIdx.x & 31u) == 0u)
            g_lutpk[wbase + (unsigned)i * 262144u] = m;
    }
}

// ---------------------------------------------------------------------------
// Fused prep: x bit-packing (grid-stride) + weight prep.
//   lo = Wp & 255  -> chunk-major u32 (4 bytes of k per word) for dp4a
//   hi = Wp >> 8 (0..6) -> 3 bitplanes over k, 8 words of 32 bits each
// ---------------------------------------------------------------------------
__global__ void k_prep(const void* __restrict__ xraw,
                       const void* __restrict__ wraw,
                       const int* __restrict__ primes) {
    const int flag = detect_u8(xraw);

    // ---- xpack: 8,388,608 bools -> 262,144 u32 words
    for (unsigned g = blockIdx.x * 256u + threadIdx.x;
         g < MSAMP * SSTEPS * 32u; g += 1024u * 256u) {
        unsigned v;
        if (flag) v = ((const unsigned char*)xraw)[g] & 1u;
        else      v = (unsigned)((const int*)xraw)[g] & 1u;
        unsigned m = __ballot_sync(0xffffffffu, v);
        if ((threadIdx.x & 31u) == 0u) g_xbits[g >> 5] = m;
    }

    // ---- wprep
    int t = blockIdx.x * 256 + threadIdx.x;
    if (t < RNODES * 8) {
        int j = t >> 3, w = t & 7;
        unsigned lo[8] = {0, 0, 0, 0, 0, 0, 0, 0};
        unsigned hb0 = 0, hb1 = 0, hb2 = 0;
        for (int kk = 0; kk < 32; kk++) {
            int k = w * 32 + kk;
            unsigned wv = flag ? (unsigned)(((const unsigned char*)wraw)[j * RNODES + k] & 1)
                               : ((unsigned)((const int*)wraw)[j * RNODES + k] & 1u);
            unsigned p = wv ? (unsigned)primes[k] : 0u;
            lo[kk >> 2] |= (p & 255u) << ((kk & 3) * 8);
            unsigned h = p >> 8;
            hb0 |= (h & 1u) << kk;
            hb1 |= ((h >> 1) & 1u) << kk;
            hb2 |= ((h >> 2) & 1u) << kk;
        }
        for (int cc = 0; cc < 8; cc++)
            g_Wlo[(w * 8 + cc) * RNODES + j] = lo[cc];
        g_hib[(0 * 8 + w) * RNODES + j] = hb0;
        g_hib[(1 * 8 + w) * RNODES + j] = hb1;
        g_hib[(2 * 8 + w) * RNODES + j] = hb2;
    }
}

// even-bit compress: keeps bits at even positions, packs into low 16
__device__ __forceinline__ unsigned unzip16(unsigned x) {
    x &= 0x55555555u;
    x = (x | (x >> 1)) & 0x33333333u;
    x = (x | (x >> 2)) & 0x0F0F0F0Fu;
    x = (x | (x >> 4)) & 0x00FF00FFu;
    x = (x | (x >> 8)) & 0x0000FFFFu;
    return x;
}

// ---------------------------------------------------------------------------
// Main reservoir kernel: 128 CTAs x 512 threads, 4 samples per CTA, occ 1.
// Thread t = (node j = t>>1, k-half h = t&1): each thread computes half the
// 256-k dot for its node (Wlo 32 regs + 12 hi-bitplane regs -> ~95 peak regs,
// fits the 128-reg cap WITHOUT spills, unlike full-dot 4-warp variants).
// Halves combine via shfl_xor(1) (partner = adjacent lane). h selects which
// sample of the active pair this thread probes. Sample pairs are software-
// pipelined as in R10: pair B's dots drain pair A's gathers and vice versa.
// State bits for the hi popcount come from the interleaved warp ballot,
// de-interleaved by lanes 0/1 into u16 halfwords (no extra barrier).
// ---------------------------------------------------------------------------
__global__ void __launch_bounds__(512, 1)
k_main(const void* __restrict__ xraw,
       const int* __restrict__ input_nodes,
       const void* __restrict__ initraw,
       const float* __restrict__ rW,
       const float* __restrict__ rb,
       float* __restrict__ out)
{
    __shared__ unsigned s_x[SPC][SSTEPS];                      // 8 KB
    __shared__ __align__(16) uint4 s_r4[SPC][16];              // 256B r-bytes per sample
    __shared__ __align__(16) unsigned short s_rb16[SPC][16];   // r-bits as 16 halfwords

    const int m0 = blockIdx.x * SPC;
    const int t = threadIdx.x;
    const int j = t >> 1;               // node 0..255
    const int h = t & 1;                // k-half & sample parity
    const int lane = t & 31, wp = t >> 5;   // wp: halfword index (nodes 16wp..16wp+15)

    // stage all samples' packed inputs (exactly one element per thread)
#pragma unroll
    for (int s = 0; s < SPC; s++)
        for (int i = t; i < SSTEPS; i += 512)
            s_x[s][i] = g_xbits[(m0 + s) * SSTEPS + i];

    // this thread's half of the weights: chunks [32h, 32h+32)
    unsigned WL[32];
#pragma unroll
    for (int c = 0; c < 32; c++) WL[c] = g_Wlo[(32 * h + c) * RNODES + j];
    unsigned HB0[4], HB1[4], HB2[4];    // hi bitplanes for words [4h, 4h+4)
#pragma unroll
    for (int w = 0; w < 4; w++) {
        HB0[w] = g_hib[(0 * 8 + 4 * h + w) * RNODES + j];
        HB1[w] = g_hib[(1 * 8 + 4 * h + w) * RNODES + j];
        HB2[w] = g_hib[(2 * 8 + 4 * h + w) * RNODES + j];
    }

    int isin = 0, ipos = 0;
    for (int i = 0; i < NIN; i++) {
        int n = input_nodes[i];
        if (n == j) { isin = 1; ipos = i; }
    }

    const int flag = detect_u8(xraw);
    unsigned rinit = flag ? (unsigned)(((const unsigned char*)initraw)[j] & 1)
                          : ((unsigned)((const int*)initraw)[j] & 1u);

    const unsigned* lutp = g_lutpk + ((unsigned)j << 13);

    // half-dot for one sample (this thread's k-range); full idx is additive
    auto halfdot = [&](int s) -> unsigned {
        const uint4* q = s_r4[s] + 8 * h;
        unsigned a0 = 0, a1 = 0, a2 = 0, a3 = 0;
#pragma unroll
        for (int u = 0; u < 8; u++) {
            uint4 v = q[u];
            a0 = __dp4a(v.x, WL[4 * u + 0], a0);
            a1 = __dp4a(v.y, WL[4 * u + 1], a1);
            a2 = __dp4a(v.z, WL[4 * u + 2], a2);
            a3 = __dp4a(v.w, WL[4 * u + 3], a3);
        }
        uint4 hw = *(const uint4*)&s_rb16[s][8 * h];
        unsigned p0 = __popc(hw.x & HB0[0]) + __popc(hw.y & HB0[1]) +
                      __popc(hw.z & HB0[2]) + __popc(hw.w & HB0[3]);
        unsigned p1 = __popc(hw.x & HB1[0]) + __popc(hw.y & HB1[1]) +
                      __popc(hw.z & HB1[2]) + __popc(hw.w & HB1[3]);
        unsigned p2 = __popc(hw.x & HB2[0]) + __popc(hw.y & HB2[1]) +
                      __popc(hw.z & HB2[2]) + __popc(hw.w & HB2[3]);
        return (a0 + a1) + (a2 + a3) + ((p0 + 2u * p1 + 4u * p2) << 8);
    };
    auto fulldot = [&](int s) -> unsigned {
        unsigned p = halfdot(s);
        return p + __shfl_xor_sync(0xffffffffu, p, 1);
    };
    // publish new state for (j, base+h): byte + interleaved-ballot bit halfwords
    auto publish_pair = [&](int base, unsigned rnew) {
        ((unsigned char*)s_r4[base + h])[j] = (unsigned char)rnew;
        unsigned bal = __ballot_sync(0xffffffffu, rnew);
        if (lane < 2) {
            // lane l extracts sample base+l's 16 node bits (positions 2i+l)
            s_rb16[base + lane][wp] = (unsigned short)unzip16(bal >> lane);
        }
    };

    __syncthreads();   // s_x visible

    // ---- prologue: state 0 (init overridden by x[0] on input nodes)
    {
        unsigned rA = isin ? ((s_x[h][0] >> ipos) & 1u) : rinit;
        unsigned rB = isin ? ((s_x[2 + h][0] >> ipos) & 1u) : rinit;
        publish_pair(0, rA);
        publish_pair(2, rB);
    }
    __syncthreads();

    // prime pair A (samples 0,1): both threads get both idxs; probe own (h)
    unsigned ia = fulldot(0), ib = fulldot(1);
    unsigned idxA = h ? ib : ia;
    unsigned wvA = __ldg(lutp + (idxA >> 5));
    __syncthreads();   // pre-loop reads of s0/s1 complete before loop rewrites

    for (int st = 0; st < SSTEPS; st++) {
        // ---- phase 1: pair B (s2,s3) dots+gather (pair A's load drains)
        unsigned i2 = fulldot(2), i3 = fulldot(3);
        unsigned idxB = h ? i3 : i2;
        unsigned wvB = __ldg(lutp + (idxB >> 5));

        // consume A(step st) -> state st+1 for own sample h
        unsigned rA = (wvA >> (idxA & 31u)) & 1u;
        if (isin && st + 1 < SSTEPS)
            rA = (s_x[h][st + 1] >> ipos) & 1u;
        publish_pair(0, rA);
        __syncthreads();

        // ---- phase 2: pair A dots+gather for st+1 (pair B's load drains)
        ia = fulldot(0); ib = fulldot(1);
        idxA = h ? ib : ia;
        wvA = __ldg(lutp + (idxA >> 5));

        // consume B(step st) -> state st+1 for own sample 2+h
        unsigned rB = (wvB >> (idxB & 31u)) & 1u;
        if (isin && st + 1 < SSTEPS)
            rB = (s_x[2 + h][st + 1] >> ipos) & 1u;
        publish_pair(2, rB);
        __syncthreads();
    }

    // final states of all 4 samples are published in s_r4 (bytes)
    // readout: out[m, o] = sum_j rW[o, j] * rf[j] + rb[o]
    if (t < SPC * 16) {                        // 64 threads: sample = t/16, out = t%16
        int s = t >> 4, o = t & 15;
        if (o < NOUT) {
            const unsigned char* rf = (const unsigned char*)s_r4[s];
            float acc = rb[o];
            const float* wr = rW + o * RNODES;
            for (int k = 0; k < RNODES; k++)
                acc += wr[k] * (float)rf[k];
            out[(m0 + s) * NOUT + o] = acc;
        }
    }
}

// ---------------------------------------------------------------------------
// d_in order: x, input_nodes, lut, W_res, primes, init_res, readout_W, readout_b
// ---------------------------------------------------------------------------
extern "C" void kernel_launch(void* const* d_in, const int* in_sizes, int n_in,
                              void* d_out, int out_size) {
    (void)in_sizes; (void)n_in; (void)out_size;
    const void*  x       = d_in[0];
    const int*   innodes = (const int*)d_in[1];
    const int*   lut     = (const int*)d_in[2];
    const void*  wres    = d_in[3];
    const int*   primes  = (const int*)d_in[4];
    const void*  initres = d_in[5];
    const float* rW      = (const float*)d_in[6];
    const float* rb      = (const float*)d_in[7];
    float* out = (float*)d_out;

    k_lutpack<<<32768, 256>>>(lut);
    k_prep<<<1024, 256>>>(x, wres, primes);
    k_main<<<NCTA, 512>>>(x, innodes, initres, rW, rb, out);
}